// round 3
// baseline (speedup 1.0000x reference)
#include <cuda_runtime.h>

#define B_DIM 256
#define T_DIM 64
#define N_DIM 2048
#define D_DIM 128

// Scratch (allocation-free: __device__ globals)
__device__ float g_ctx_term[B_DIM * N_DIM];   // 2 MB
__device__ float g_tgt_term[B_DIM];
__device__ float g_attn[B_DIM * N_DIM];       // 2 MB

// ---------------------------------------------------------------------------
// Kernel A: ctx_term[row] = dot(ctx[row, 0:128], W[128:256])
// One warp per row: lane loads one float4 (512B per warp, fully coalesced).
// ---------------------------------------------------------------------------
__global__ void ctx_dot_kernel(const float* __restrict__ ctx,
                               const float* __restrict__ W) {
    const int warp = (blockIdx.x * blockDim.x + threadIdx.x) >> 5;
    const int lane = threadIdx.x & 31;

    const float4 c = __ldg((const float4*)(ctx) + (size_t)warp * (D_DIM / 4) + lane);
    const float4 w = __ldg((const float4*)(W + D_DIM) + lane);

    float s = c.x * w.x + c.y * w.y + c.z * w.z + c.w * w.w;
    #pragma unroll
    for (int o = 16; o; o >>= 1) s += __shfl_xor_sync(0xffffffffu, s, o);

    if (lane == 0) g_ctx_term[warp] = s;
}

// ---------------------------------------------------------------------------
// Kernel A2: tgt_term[b] = sum_{t,d} tgt[b,t,d] * W[d]
// One block (256 threads) per batch; 8192 elements reduced per block.
// ---------------------------------------------------------------------------
__global__ void tgt_dot_kernel(const float* __restrict__ tgt,
                               const float* __restrict__ W) {
    const int b   = blockIdx.x;
    const int tid = threadIdx.x;
    const float4* base = (const float4*)(tgt + (size_t)b * T_DIM * D_DIM);

    float s = 0.f;
    #pragma unroll
    for (int i = tid; i < (T_DIM * D_DIM) / 4; i += 256) {
        float4 v = __ldg(base + i);
        float4 w = __ldg((const float4*)W + (i & (D_DIM / 4 - 1)));
        s += v.x * w.x + v.y * w.y + v.z * w.z + v.w * w.w;
    }

    __shared__ float red[256];
    red[tid] = s;
    __syncthreads();
    #pragma unroll
    for (int o = 128; o; o >>= 1) {
        if (tid < o) red[tid] += red[tid + o];
        __syncthreads();
    }
    if (tid == 0) g_tgt_term[b] = red[0];
}

// ---------------------------------------------------------------------------
// Kernel B: per-batch softmax of scores -> g_attn
// scores[b,n] = tgt_term[b] + T * (ctx_term[b,n] + b0)
// ---------------------------------------------------------------------------
__global__ void softmax_kernel(const float* __restrict__ bias) {
    const int b   = blockIdx.x;
    const int tid = threadIdx.x;  // 256 threads

    __shared__ float s_sc[N_DIM];   // 8 KB
    __shared__ float red[256];

    const float b0 = __ldg(bias);
    const float tt = g_tgt_term[b];
    const float* ct = g_ctx_term + (size_t)b * N_DIM;

    float lmax = -1e30f;
    #pragma unroll
    for (int i = tid; i < N_DIM; i += 256) {
        float sc = fmaf((float)T_DIM, ct[i] + b0, tt);
        s_sc[i] = sc;
        lmax = fmaxf(lmax, sc);
    }
    red[tid] = lmax;
    __syncthreads();
    #pragma unroll
    for (int o = 128; o; o >>= 1) {
        if (tid < o) red[tid] = fmaxf(red[tid], red[tid + o]);
        __syncthreads();
    }
    const float m = red[0];
    __syncthreads();

    float lsum = 0.f;
    #pragma unroll
    for (int i = tid; i < N_DIM; i += 256) {
        float e = __expf(s_sc[i] - m);
        s_sc[i] = e;
        lsum += e;
    }
    red[tid] = lsum;
    __syncthreads();
    #pragma unroll
    for (int o = 128; o; o >>= 1) {
        if (tid < o) red[tid] += red[tid + o];
        __syncthreads();
    }
    const float inv = 1.f / red[0];
    __syncthreads();

    float* at = g_attn + (size_t)b * N_DIM;
    #pragma unroll
    for (int i = tid; i < N_DIM; i += 256) at[i] = s_sc[i] * inv;
}

// ---------------------------------------------------------------------------
// Kernel C: out[b,n,d] = attn[b,n] * ctx[b,n,d]   (pure streaming, float4)
// idx >> 5 maps a float4 index to its (b,n) row (128 floats = 32 float4 / row).
// Each warp touches exactly one attn value (broadcast within warp).
// ---------------------------------------------------------------------------
__global__ void scale_kernel(const float* __restrict__ ctx,
                             float* __restrict__ out) {
    const size_t idx = (size_t)blockIdx.x * blockDim.x + threadIdx.x;
    const float  a = g_attn[idx >> 5];
    const float4 c = __ldg((const float4*)ctx + idx);
    float4 o;
    o.x = a * c.x; o.y = a * c.y; o.z = a * c.z; o.w = a * c.w;
    ((float4*)out)[idx] = o;
}

// ---------------------------------------------------------------------------
extern "C" void kernel_launch(void* const* d_in, const int* in_sizes, int n_in,
                              void* d_out, int out_size) {
    const float* tgt  = (const float*)d_in[0];  // (256, 64, 128) f32
    const float* ctx  = (const float*)d_in[1];  // (256, 2048, 128) f32
    const float* W    = (const float*)d_in[2];  // (256,) f32
    const float* bias = (const float*)d_in[3];  // (1,) f32
    float* out = (float*)d_out;                 // (256, 2048, 128) f32

    // A: 524288 rows, 8 warps/block -> 65536 blocks
    ctx_dot_kernel<<<(B_DIM * N_DIM) / 8, 256>>>(ctx, W);
    // A2: one block per batch
    tgt_dot_kernel<<<B_DIM, 256>>>(tgt, W);
    // B: one block per batch
    softmax_kernel<<<B_DIM, 256>>>(bias);
    // C: 16777216 float4 / 256 threads = 65536 blocks (exact)
    scale_kernel<<<(B_DIM * N_DIM * (D_DIM / 4)) / 256, 256>>>(ctx, out);
}